// round 6
// baseline (speedup 1.0000x reference)
#include <cuda_runtime.h>
#include <stdint.h>

// Problem dims
#define BSZ   4096
#define INF   1024
#define OUTF  2048
#define BF    8388608u     // BSZ*OUTF (per-timestep element count)

// libdevice precise functions (immune to fast-math substitution)
extern "C" __device__ float __nv_logf(float);
extern "C" __device__ float __nv_rsqrtf(float);

// Scratch for raw = x@W.T + b  (device global: no allocation allowed)
__device__ float g_raw[BSZ * OUTF];

// ---------------------------------------------------------------------------
// Kernel 1: fp32 SGEMM  raw[m,n] = sum_k x[m,k]*W[n,k] + b[n]
// 128x128 tile, BK=16, 256 threads, 8x8 microtile, single accumulator,
// k strictly ascending (closest match to cuBLAS fp32 accumulation order).
// ---------------------------------------------------------------------------
__global__ __launch_bounds__(256, 2)
void gemm_kernel(const float* __restrict__ X, const float* __restrict__ W,
                 const float* __restrict__ bias, float* __restrict__ out)
{
    __shared__ float As[16][128];
    __shared__ float Bs[16][128];

    const int n0 = blockIdx.x * 128;
    const int m0 = blockIdx.y * 128;
    const int tid = threadIdx.x;
    const int tn = (tid & 15) * 8;
    const int tm = (tid >> 4) * 8;

    const int qrow = tid >> 2;        // 0..63
    const int qcol = (tid & 3) * 4;   // 0,4,8,12
    const float* xptr = X + (size_t)(m0 + qrow) * INF + qcol;
    const float* wptr = W + (size_t)(n0 + qrow) * INF + qcol;

    float c[8][8];
#pragma unroll
    for (int i = 0; i < 8; i++)
#pragma unroll
        for (int j = 0; j < 8; j++) c[i][j] = 0.0f;

    float4 ar[2], br[2];
    ar[0] = *(const float4*)(xptr);
    ar[1] = *(const float4*)(xptr + (size_t)64 * INF);
    br[0] = *(const float4*)(wptr);
    br[1] = *(const float4*)(wptr + (size_t)64 * INF);

    for (int kt = 0; kt < INF / 16; kt++) {
#pragma unroll
        for (int s = 0; s < 2; s++) {
            const int row = qrow + s * 64;
            As[qcol + 0][row] = ar[s].x; As[qcol + 1][row] = ar[s].y;
            As[qcol + 2][row] = ar[s].z; As[qcol + 3][row] = ar[s].w;
            Bs[qcol + 0][row] = br[s].x; Bs[qcol + 1][row] = br[s].y;
            Bs[qcol + 2][row] = br[s].z; Bs[qcol + 3][row] = br[s].w;
        }
        __syncthreads();

        if (kt < INF / 16 - 1) {
            const float* xp = xptr + (kt + 1) * 16;
            const float* wp = wptr + (kt + 1) * 16;
            ar[0] = *(const float4*)(xp);
            ar[1] = *(const float4*)(xp + (size_t)64 * INF);
            br[0] = *(const float4*)(wp);
            br[1] = *(const float4*)(wp + (size_t)64 * INF);
        }

#pragma unroll
        for (int k = 0; k < 16; k++) {
            float4 a0 = *(const float4*)(&As[k][tm]);
            float4 a1 = *(const float4*)(&As[k][tm + 4]);
            float4 b0 = *(const float4*)(&Bs[k][tn]);
            float4 b1 = *(const float4*)(&Bs[k][tn + 4]);
            float av[8] = {a0.x, a0.y, a0.z, a0.w, a1.x, a1.y, a1.z, a1.w};
            float bv[8] = {b0.x, b0.y, b0.z, b0.w, b1.x, b1.y, b1.z, b1.w};
#pragma unroll
            for (int i = 0; i < 8; i++)
#pragma unroll
                for (int j = 0; j < 8; j++)
                    c[i][j] = fmaf(av[i], bv[j], c[i][j]);
        }
        __syncthreads();
    }

#pragma unroll
    for (int i = 0; i < 8; i++) {
        float* orow = out + (size_t)(m0 + tm + i) * OUTF + n0 + tn;
#pragma unroll
        for (int j = 0; j < 8; j++)
            orow[j] = __fadd_rn(c[i][j], bias[n0 + tn + j]);
    }
}

// ---------------------------------------------------------------------------
// JAX threefry2x32, key = (0, 42)
// ---------------------------------------------------------------------------
__device__ __forceinline__ void tf2x32(uint32_t x0, uint32_t x1,
                                       uint32_t& r0, uint32_t& r1)
{
    const uint32_t ks0 = 0u;
    const uint32_t ks1 = 42u;
    const uint32_t ks2 = 0x1BD11BDAu ^ 42u;
#define TFR(r) { x0 += x1; x1 = __funnelshift_l(x1, x1, (r)); x1 ^= x0; }
    x0 += ks0; x1 += ks1;
    TFR(13) TFR(15) TFR(26) TFR(6)
    x0 += ks1; x1 += ks2 + 1u;
    TFR(17) TFR(29) TFR(16) TFR(24)
    x0 += ks2; x1 += ks0 + 2u;
    TFR(13) TFR(15) TFR(26) TFR(6)
    x0 += ks0; x1 += ks1 + 3u;
    TFR(17) TFR(29) TFR(16) TFR(24)
    x0 += ks1; x1 += ks2 + 4u;
    TFR(13) TFR(15) TFR(26) TFR(6)
    x0 += ks2; x1 += ks0 + 5u;
#undef TFR
    r0 = x0; r1 = x1;
}

// bits -> 0.3 * (sqrt(2) * erfinv(u)),  u in [-1+ulp, 1)
// Exactly mirrors XLA: uniform bit trick, EmitLog1p, Giles erfinv (unfused).
__device__ __forceinline__ float bits_to_noise(uint32_t bits)
{
    float f = __fsub_rn(__uint_as_float((bits >> 9) | 0x3f800000u), 1.0f);
    float u = __fadd_rn(__fmul_rn(f, 2.0f), -0.99999994f);
    u = fmaxf(u, -0.99999994f);

    // w = -log1p(-u*u), XLA EmitLog1p: |x|<1e-4 ? x*(1 - 0.5x) : log(1+x)
    float y = -__fmul_rn(u, u);
    float w;
    if (fabsf(y) < 1e-4f) {
        w = __fmul_rn(__fadd_rn(__fmul_rn(-0.5f, y), 1.0f), y);
    } else {
        w = __nv_logf(__fadd_rn(y, 1.0f));
    }
    w = -w;

    float p;
    if (w < 5.0f) {
        w = __fsub_rn(w, 2.5f);
        p = 2.81022636e-08f;
        p = __fadd_rn(__fmul_rn(p, w),  3.43273939e-07f);
        p = __fadd_rn(__fmul_rn(p, w), -3.5233877e-06f);
        p = __fadd_rn(__fmul_rn(p, w), -4.39150654e-06f);
        p = __fadd_rn(__fmul_rn(p, w),  0.00021858087f);
        p = __fadd_rn(__fmul_rn(p, w), -0.00125372503f);
        p = __fadd_rn(__fmul_rn(p, w), -0.00417768164f);
        p = __fadd_rn(__fmul_rn(p, w),  0.246640727f);
        p = __fadd_rn(__fmul_rn(p, w),  1.50140941f);
    } else {
        w = __fsub_rn(__fsqrt_rn(w), 3.0f);
        p = -0.000200214257f;
        p = __fadd_rn(__fmul_rn(p, w),  0.000100950558f);
        p = __fadd_rn(__fmul_rn(p, w),  0.00134934322f);
        p = __fadd_rn(__fmul_rn(p, w), -0.00367342844f);
        p = __fadd_rn(__fmul_rn(p, w),  0.00573950773f);
        p = __fadd_rn(__fmul_rn(p, w), -0.0076224613f);
        p = __fadd_rn(__fmul_rn(p, w),  0.00943887047f);
        p = __fadd_rn(__fmul_rn(p, w),  1.00167406f);
        p = __fadd_rn(__fmul_rn(p, w),  2.83297682f);
    }
    float r = __fmul_rn(p, u);                 // erfinv(u)
    r = __fmul_rn(1.41421356f, r);             // sqrt(2) * erfinv
    return __fmul_rn(0.3f, r);                 // NOISE_STD * normal
}

// XLA f32 rational tanh (elemental IR emitter, unfused ops)
__device__ __forceinline__ float xla_tanhf(float x)
{
    float ax = fabsf(x);
    float xc = fminf(fmaxf(x, -7.90531110763549805f), 7.90531110763549805f);
    float x2 = __fmul_rn(xc, xc);
    float np_ = -2.76076847742355e-16f;
    np_ = __fadd_rn(__fmul_rn(np_, x2),  2.00018790482477e-13f);
    np_ = __fadd_rn(__fmul_rn(np_, x2), -8.60467152213735e-11f);
    np_ = __fadd_rn(__fmul_rn(np_, x2),  5.12229709037114e-08f);
    np_ = __fadd_rn(__fmul_rn(np_, x2),  1.48572235717979e-05f);
    np_ = __fadd_rn(__fmul_rn(np_, x2),  6.37261928875436e-04f);
    np_ = __fadd_rn(__fmul_rn(np_, x2),  4.89352455891786e-03f);
    np_ = __fmul_rn(np_, xc);
    float dp = 1.19825839466702e-06f;
    dp = __fadd_rn(__fmul_rn(dp, x2),  1.18534705686654e-04f);
    dp = __fadd_rn(__fmul_rn(dp, x2),  2.26843463243900e-03f);
    dp = __fadd_rn(__fmul_rn(dp, x2),  4.89352518554385e-03f);
    float r = __fdiv_rn(np_, dp);
    return (ax < 0.0004f) ? x : r;
}

__device__ __forceinline__ float block_reduce(float v, float* sbuf, int tid)
{
#pragma unroll
    for (int o = 16; o > 0; o >>= 1) v += __shfl_xor_sync(0xffffffffu, v, o);
    if ((tid & 31) == 0) sbuf[tid >> 5] = v;
    __syncthreads();
    if (tid < 8) {
        float t = sbuf[tid];
#pragma unroll
        for (int o = 4; o > 0; o >>= 1) t += __shfl_xor_sync(0xffu, t, o);
        if (tid == 0) sbuf[0] = t;
    }
    __syncthreads();
    float r = sbuf[0];
    __syncthreads();
    return r;
}

// ---------------------------------------------------------------------------
// Kernel 2: LN + tanh scaling + partitionable-threefry noise + 8-step
// Izhikevich, fused. One CTA per batch row; 256 threads x 8 features.
// Noise element (t,b,f): counter = (0, t*BF + b*OUTF + f), bits = r0 ^ r1.
// ---------------------------------------------------------------------------
__global__ __launch_bounds__(256)
void snn_kernel(const float* __restrict__ raw_g,
                const float* __restrict__ gamma, const float* __restrict__ beta,
                const float* __restrict__ cmag, float* __restrict__ out)
{
    __shared__ float sbuf[8];
    const int b = blockIdx.x;
    const int tid = threadIdx.x;
    const float* rowp = raw_g + (size_t)b * OUTF;

    float vals[8];
    float s = 0.0f;
#pragma unroll
    for (int j = 0; j < 8; j++) {
        vals[j] = rowp[tid + 256 * j];
        s += vals[j];
    }
    s = block_reduce(s, sbuf, tid);
    const float mu = __fmul_rn(s, (1.0f / 2048.0f));   // exact /2048

    float s2 = 0.0f;
#pragma unroll
    for (int j = 0; j < 8; j++) {
        float d = __fsub_rn(vals[j], mu);
        s2 += __fmul_rn(d, d);
    }
    s2 = block_reduce(s2, sbuf, tid);
    const float var = __fmul_rn(s2, (1.0f / 2048.0f));
    const float rstd = __nv_rsqrtf(__fadd_rn(var, 1e-5f));
    const float imag = fabsf(cmag[0]);

#pragma unroll 1
    for (int j = 0; j < 8; j++) {
        const int f = tid + 256 * j;
        const float d  = __fsub_rn(vals[j], mu);
        const float ln = __fadd_rn(__fmul_rn(__fmul_rn(d, rstd), gamma[f]), beta[f]);
        const float I  = __fmul_rn(xla_tanhf(ln), imag);

        // partitionable threefry: one independent block per timestep
        const uint32_t e = (uint32_t)b * (uint32_t)OUTF + (uint32_t)f;
        float nz[8];
#pragma unroll
        for (int t = 0; t < 8; t++) {
            uint32_t r0, r1;
            tf2x32(0u, (uint32_t)t * BF + e, r0, r1);
            nz[t] = bits_to_noise(r0 ^ r1);
        }

        float v = -65.0f, uu = -13.0f, acc = 0.0f;
#pragma unroll
        for (int t = 0; t < 8; t++) {
            const float It = __fadd_rn(I, nz[t]);
            // dv = ((0.04*v)*v + 5*v + 140 - u + I_t) * DT, all unfused
            float t1 = __fmul_rn(__fmul_rn(0.04f, v), v);
            float t2 = __fmul_rn(5.0f, v);
            float sdv = __fadd_rn(t1, t2);
            sdv = __fadd_rn(sdv, 140.0f);
            sdv = __fsub_rn(sdv, uu);
            sdv = __fadd_rn(sdv, It);
            const float vn = fminf(fmaxf(__fadd_rn(v, sdv), -100.0f), 60.0f);
            // du = 0.02*(0.2*v - u)
            float tu = __fsub_rn(__fmul_rn(0.2f, v), uu);
            tu = __fmul_rn(0.02f, tu);
            const float un = fminf(fmaxf(__fadd_rn(uu, tu), -100.0f), 100.0f);
            const bool spk = (vn >= 30.0f);
            v  = spk ? -65.0f : vn;
            uu = spk ? __fadd_rn(un, 8.0f) : un;
            acc += spk ? 1.0f : 0.0f;
        }
        out[(size_t)b * OUTF + f] = __fmul_rn(acc, 0.125f);
    }
}

// ---------------------------------------------------------------------------
extern "C" void kernel_launch(void* const* d_in, const int* in_sizes, int n_in,
                              void* d_out, int out_size)
{
    const float* x     = (const float*)d_in[0];  // [4096,1024]
    const float* W     = (const float*)d_in[1];  // [2048,1024]
    const float* b_lin = (const float*)d_in[2];  // [2048]
    const float* gamma = (const float*)d_in[3];  // [2048]
    const float* beta  = (const float*)d_in[4];  // [2048]
    const float* cmag  = (const float*)d_in[5];  // [1]
    float* out = (float*)d_out;                  // [4096,2048]

    float* raw;
    cudaGetSymbolAddress((void**)&raw, g_raw);

    dim3 ggrid(OUTF / 128, BSZ / 128);
    gemm_kernel<<<ggrid, 256>>>(x, W, b_lin, raw);
    snn_kernel<<<BSZ, 256>>>(raw, gamma, beta, cmag, out);
}